// round 4
// baseline (speedup 1.0000x reference)
#include <cuda_runtime.h>
#include <cuda_bf16.h>
#include <math.h>

// ---------------------------------------------------------------------------
// HybridKANModel: conv1+pool -> conv2+pool -> KAN(hat basis, 50 grid) ->
//                 SimplifiedKAN -> dense -> softmax.  B=4096, fp32 throughout.
//
// KAN1 (the 13.4 GF einsum) is restructured as an exact piecewise-linear
// evaluation: f_{o,d}(x) = c0[d,k,o] + c1[d,k,o]*x with k = floor(49*x),
// 98 uniform segments on [0,2), zero for x>=2.  Tables precomputed per call.
// ---------------------------------------------------------------------------

#define B_TOTAL 4096

// scratch (static device globals; no allocation allowed)
__device__ float g_h1[B_TOTAL * 6 * 6 * 32];     // 18.9 MB
__device__ float g_h2[B_TOTAL * 256];            // 4 MB  (flattened NHWC of 2x2x64)
__device__ float g_C0[256 * 98 * 128];           // 12.85 MB
__device__ float g_C1[256 * 98 * 128];           // 12.85 MB
__device__ float g_out1[B_TOTAL * 128];          // 2 MB

// ---------------------------------------------------------------------------
// K1: conv1 (3x3, 1->32, VALID) + ReLU + maxpool2  : x(B,14,14,1) -> h1(B,6,6,32)
// one block per batch element, 128 threads
// ---------------------------------------------------------------------------
__global__ void conv1_pool_kernel(const float* __restrict__ x,
                                  const float* __restrict__ w,
                                  const float* __restrict__ bias) {
    int b = blockIdx.x;
    __shared__ float xs[196];     // 14x14
    __shared__ float ws[288];     // [ky][kx][c]
    __shared__ float bs[32];
    int t = threadIdx.x;
    for (int i = t; i < 196; i += 128) xs[i] = x[b * 196 + i];
    for (int i = t; i < 288; i += 128) ws[i] = w[i];
    if (t < 32) bs[t] = bias[t];
    __syncthreads();

    for (int idx = t; idx < 1152; idx += 128) {
        int c = idx & 31;
        int pos = idx >> 5;            // 0..35
        int py = pos / 6, px = pos % 6;
        float best = -3.0e38f;
        #pragma unroll
        for (int dy = 0; dy < 2; dy++) {
            #pragma unroll
            for (int dx = 0; dx < 2; dx++) {
                int y = 2 * py + dy, xx = 2 * px + dx;
                float acc = bs[c];
                #pragma unroll
                for (int ky = 0; ky < 3; ky++)
                    #pragma unroll
                    for (int kx = 0; kx < 3; kx++)
                        acc = fmaf(xs[(y + ky) * 14 + xx + kx],
                                   ws[(ky * 3 + kx) * 32 + c], acc);
                best = fmaxf(best, acc);
            }
        }
        g_h1[b * 1152 + idx] = fmaxf(best, 0.0f);   // relu(max) == max(relu)
    }
}

// ---------------------------------------------------------------------------
// K2: conv2 (3x3, 32->64, VALID) + ReLU + maxpool2 : h1(B,6,6,32) -> h2(B,256)
// one block per batch element, 256 threads (thread = one pooled output)
// ---------------------------------------------------------------------------
__global__ void conv2_pool_kernel(const float* __restrict__ w2,
                                  const float* __restrict__ b2) {
    int b = blockIdx.x;
    __shared__ float hs[1152];    // 6x6x32
    int t = threadIdx.x;          // 256
    for (int i = t; i < 1152; i += 256) hs[i] = g_h1[b * 1152 + i];
    __syncthreads();

    int c = t & 63;
    int pos = t >> 6;             // 0..3
    int py = pos >> 1, px = pos & 1;

    float a00 = b2[c], a01 = b2[c], a10 = b2[c], a11 = b2[c];
    #pragma unroll
    for (int ky = 0; ky < 3; ky++) {
        #pragma unroll
        for (int kx = 0; kx < 3; kx++) {
            const float* wrow = w2 + ((ky * 3 + kx) * 32) * 64 + c;
            int ybase0 = (2 * py + 0 + ky) * 6 + (2 * px + kx);
            int ybase1 = (2 * py + 1 + ky) * 6 + (2 * px + kx);
            #pragma unroll
            for (int i = 0; i < 32; i++) {
                float wv  = wrow[i * 64];
                float x00 = hs[(ybase0 + 0) * 32 + i];
                float x01 = hs[(ybase0 + 1) * 32 + i];
                float x10 = hs[(ybase1 + 0) * 32 + i];
                float x11 = hs[(ybase1 + 1) * 32 + i];
                a00 = fmaf(x00, wv, a00);
                a01 = fmaf(x01, wv, a01);
                a10 = fmaf(x10, wv, a10);
                a11 = fmaf(x11, wv, a11);
            }
        }
    }
    float best = fmaxf(fmaxf(a00, a01), fmaxf(a10, a11));
    g_h2[b * 256 + t] = fmaxf(best, 0.0f);
}

// ---------------------------------------------------------------------------
// K3: KAN1 piecewise-linear table precompute.
//  f_{o,d}(x) = sum_g W[o,d,g] * relu(1 - |x - g/49|)  is PWL with knots m/49.
//  Segment k (x in (k/49,(k+1)/49), k=0..97): active g in [max(0,k-48), 49].
//    c1 = SW_hi - SW_lo      (SW_lo over active g<=k, SW_hi over g>k)
//    c0 = (49*(SW_lo+SW_hi) + SWG_lo - SWG_hi) / 49
//  grid = 256 (d), block = 128 (o)
// ---------------------------------------------------------------------------
__global__ void kan1_precompute_kernel(const float* __restrict__ kw) {
    int d = blockIdx.x;
    int o = threadIdx.x;
    const float* W = kw + (o * 256 + d) * 50;

    float P[51], Q[51];
    P[0] = 0.0f; Q[0] = 0.0f;
    for (int g = 0; g < 50; g++) {
        float w = W[g];
        P[g + 1] = P[g] + w;
        Q[g + 1] = Q[g] + w * (float)g;
    }
    for (int k = 0; k < 98; k++) {
        int a = k - 48; if (a < 0) a = 0;
        int hi_lo = (k < 49) ? k : 49;           // min(k,49)
        float SWlo  = P[hi_lo + 1] - P[a];
        float SWGlo = Q[hi_lo + 1] - Q[a];
        float SWhi = 0.0f, SWGhi = 0.0f;
        if (k < 49) { SWhi = P[50] - P[k + 1]; SWGhi = Q[50] - Q[k + 1]; }
        float c1 = SWhi - SWlo;
        float c0 = (49.0f * (SWlo + SWhi) + SWGlo - SWGhi) * (1.0f / 49.0f);
        g_C0[(d * 98 + k) * 128 + o] = c0;
        g_C1[(d * 98 + k) * 128 + o] = c1;
    }
}

// ---------------------------------------------------------------------------
// K4: KAN1 eval: out1[b,o] = sum_d c0[d,k(b,d),o] + x*c1[d,k(b,d),o]
// block = 256 threads = 8 warps = 8 batch rows; each lane owns 4 o's via float4
// ---------------------------------------------------------------------------
__global__ void kan1_eval_kernel() {
    __shared__ float hs[8 * 256];
    int t = threadIdx.x;
    int blk = blockIdx.x;                 // 512 blocks
    int base = blk * 8 * 256;
    for (int i = t; i < 2048; i += 256) hs[i] = g_h2[base + i];
    __syncthreads();

    int w = t >> 5, lane = t & 31;
    const float* hrow = hs + w * 256;
    float4 acc = make_float4(0.f, 0.f, 0.f, 0.f);

    #pragma unroll 2
    for (int d = 0; d < 256; d++) {
        float x = hrow[d];                // warp-uniform broadcast
        if (x < 2.0f) {
            int k = (int)(x * 49.0f);
            if (k > 97) k = 97;
            const float4* p0 = (const float4*)(g_C0 + (d * 98 + k) * 128) + lane;
            const float4* p1 = (const float4*)(g_C1 + (d * 98 + k) * 128) + lane;
            float4 v0 = *p0;
            float4 v1 = *p1;
            acc.x = fmaf(x, v1.x, acc.x + v0.x);
            acc.y = fmaf(x, v1.y, acc.y + v0.y);
            acc.z = fmaf(x, v1.z, acc.z + v0.z);
            acc.w = fmaf(x, v1.w, acc.w + v0.w);
        }
    }
    int b = blk * 8 + w;
    ((float4*)(g_out1 + b * 128))[lane] = acc;
}

// ---------------------------------------------------------------------------
// K5: relu -> kan2 (64,128) -> dense (64,10) -> softmax.  block per b, 64 thr.
// ---------------------------------------------------------------------------
__global__ void final_kernel(const float* __restrict__ w2,
                             const float* __restrict__ dw,
                             const float* __restrict__ db,
                             float* __restrict__ out) {
    int b = blockIdx.x;
    int t = threadIdx.x;                  // 64
    __shared__ float hs[128];
    __shared__ float os[64];
    __shared__ float ls[10];

    hs[t]      = fmaxf(g_out1[b * 128 + t], 0.0f);
    hs[t + 64] = fmaxf(g_out1[b * 128 + 64 + t], 0.0f);
    __syncthreads();

    float s = 0.0f;
    const float* wr = w2 + t * 128;
    #pragma unroll 8
    for (int d = 0; d < 128; d++) s = fmaf(wr[d], hs[d], s);
    os[t] = s;
    __syncthreads();

    if (t < 10) {
        float l = db[t];
        #pragma unroll 8
        for (int j = 0; j < 64; j++) l = fmaf(os[j], dw[j * 10 + t], l);
        ls[t] = l;
    }
    __syncthreads();
    if (t < 10) {
        float m = ls[0];
        #pragma unroll
        for (int c = 1; c < 10; c++) m = fmaxf(m, ls[c]);
        float sum = 0.0f;
        #pragma unroll
        for (int c = 0; c < 10; c++) sum += expf(ls[c] - m);
        out[b * 10 + t] = expf(ls[t] - m) / sum;
    }
}

// ---------------------------------------------------------------------------
extern "C" void kernel_launch(void* const* d_in, const int* in_sizes, int n_in,
                              void* d_out, int out_size) {
    // Map inputs defensively by element count (all counts are distinct).
    const float *x = 0, *c1w = 0, *c1b = 0, *c2w = 0, *c2b = 0;
    const float *k1w = 0, *k2w = 0, *dw = 0, *db = 0;
    for (int i = 0; i < n_in; i++) {
        switch (in_sizes[i]) {
            case 802816:  x   = (const float*)d_in[i]; break;
            case 288:     c1w = (const float*)d_in[i]; break;
            case 32:      c1b = (const float*)d_in[i]; break;
            case 18432:   c2w = (const float*)d_in[i]; break;
            case 64:      c2b = (const float*)d_in[i]; break;
            case 50:      /* grid: exact uniform linspace(0,1,50), folded into tables */ break;
            case 1638400: k1w = (const float*)d_in[i]; break;
            case 8192:    k2w = (const float*)d_in[i]; break;
            case 640:     dw  = (const float*)d_in[i]; break;
            case 10:      db  = (const float*)d_in[i]; break;
            default: break;
        }
    }
    float* out = (float*)d_out;

    conv1_pool_kernel<<<B_TOTAL, 128>>>(x, c1w, c1b);
    kan1_precompute_kernel<<<256, 128>>>(k1w);     // independent of convs
    conv2_pool_kernel<<<B_TOTAL, 256>>>(c2w, c2b);
    kan1_eval_kernel<<<B_TOTAL / 8, 256>>>();
    final_kernel<<<B_TOTAL, 64>>>(k2w, dw, db, out);
}